// round 4
// baseline (speedup 1.0000x reference)
#include <cuda_runtime.h>

#define NB 256
#define NC 4096
#define NK 32
#define THREADS 512
#define EPT 8  // elements per thread: THREADS*EPT == NC

__device__ __forceinline__ unsigned long long add_f32x2(unsigned long long a,
                                                        unsigned long long b) {
    unsigned long long r;
    asm("add.rn.f32x2 %0, %1, %2;" : "=l"(r) : "l"(a), "l"(b));
    return r;
}

__device__ __forceinline__ unsigned long long pack2(float lo, float hi) {
    unsigned long long r;
    asm("mov.b64 %0, {%1, %2};" : "=l"(r) : "f"(lo), "f"(hi));
    return r;
}

__device__ __forceinline__ float2 unpack2(unsigned long long v) {
    float lo, hi;
    asm("mov.b64 {%0, %1}, %2;" : "=f"(lo), "=f"(hi) : "l"(v));
    return make_float2(lo, hi);
}

__global__ void init_out_kernel(float* out) { out[0] = 0.0f; }

__global__ __launch_bounds__(THREADS, 2)
void mlaml_kernel(const float* __restrict__ x, const float* __restrict__ m,
                  const int* __restrict__ tgt, float* __restrict__ out) {
    __shared__ float c_sh[NK];
    __shared__ float warp_sum[THREADS / 32];
    __shared__ float D_sh;
    __shared__ float sumc_sh;
    __shared__ int V_sh;

    const int b   = blockIdx.x;
    const int tid = threadIdx.x;
    const int wid = tid >> 5;
    const int lid = tid & 31;

    const float* xr = x + (size_t)b * NC;
    const float* mr = m + (size_t)b * NC;

    // ---- Load this thread's 8 contiguous d_j = x_j - m_j, pack into f32x2 ----
    const int j0 = tid * EPT;
    float4 xa = *reinterpret_cast<const float4*>(xr + j0);
    float4 xb = *reinterpret_cast<const float4*>(xr + j0 + 4);
    float4 ma = *reinterpret_cast<const float4*>(mr + j0);
    float4 mb = *reinterpret_cast<const float4*>(mr + j0 + 4);

    float ds[EPT];
    ds[0] = xa.x - ma.x; ds[1] = xa.y - ma.y;
    ds[2] = xa.z - ma.z; ds[3] = xa.w - ma.w;
    ds[4] = xb.x - mb.x; ds[5] = xb.y - mb.y;
    ds[6] = xb.z - mb.z; ds[7] = xb.w - mb.w;

    unsigned long long d2[4];
    d2[0] = pack2(ds[0], ds[1]);
    d2[1] = pack2(ds[2], ds[3]);
    d2[2] = pack2(ds[4], ds[5]);
    d2[3] = pack2(ds[6], ds[7]);

    // ---- Warp 0: gather targets, compute c_k = 1 - d_t, compact valid ones ----
    if (tid < NK) {
        int t     = tgt[b * NK + tid];          // int32 targets (JAX x64 disabled)
        int valid = (t > -1) ? 1 : 0;
        float c   = 0.0f;
        if (valid) {
            c = 1.0f - (__ldg(xr + t) - __ldg(mr + t));
        }
        unsigned mask = __ballot_sync(0xffffffffu, valid);
        int pos = __popc(mask & ((1u << tid) - 1u));
        if (valid) c_sh[pos] = c;
        float cs = valid ? c : 0.0f;
        #pragma unroll
        for (int off = 16; off; off >>= 1)
            cs += __shfl_xor_sync(0xffffffffu, cs, off);
        if (tid == 0) { V_sh = __popc(mask); sumc_sh = cs; }
    }

    // ---- Row sum D = sum_j d_j (block reduce) ----
    float dloc = ((ds[0] + ds[1]) + (ds[2] + ds[3])) +
                 ((ds[4] + ds[5]) + (ds[6] + ds[7]));
    #pragma unroll
    for (int off = 16; off; off >>= 1)
        dloc += __shfl_xor_sync(0xffffffffu, dloc, off);
    if (lid == 0) warp_sum[wid] = dloc;
    __syncthreads();
    if (tid == 0) {
        float D = 0.0f;
        #pragma unroll
        for (int i = 0; i < THREADS / 32; i++) D += warp_sum[i];
        D_sh = D;
    }
    __syncthreads();  // D_sh ready; c_sh / V_sh / sumc_sh visible to all

    // ---- Main loop: sum |c_k + d_j| over valid k, packed f32x2 + LOP3 abs ----
    const int V = V_sh;
    const unsigned long long ABSM = 0x7fffffff7fffffffULL;
    unsigned long long acc[4] = {0ull, 0ull, 0ull, 0ull};  // packed (+0,+0)

    for (int kk = 0; kk < V; kk++) {
        float c = c_sh[kk];
        unsigned long long c2 = pack2(c, c);
        #pragma unroll
        for (int r = 0; r < 4; r++) {
            unsigned long long t2 = add_f32x2(c2, d2[r]);
            t2 &= ABSM;                       // 2x LOP3 -> |lo|,|hi|
            acc[r] = add_f32x2(acc[r], t2);
        }
    }

    float2 a0 = unpack2(acc[0]);
    float2 a1 = unpack2(acc[1]);
    float2 a2 = unpack2(acc[2]);
    float2 a3 = unpack2(acc[3]);
    float local = ((a0.x + a0.y) + (a1.x + a1.y)) +
                  ((a2.x + a2.y) + (a3.x + a3.y));

    // ---- Block reduce abs-sum, combine with analytic part, atomicAdd ----
    #pragma unroll
    for (int off = 16; off; off >>= 1)
        local += __shfl_xor_sync(0xffffffffu, local, off);
    if (lid == 0) warp_sum[wid] = local;
    __syncthreads();
    if (tid == 0) {
        float tot = 0.0f;
        #pragma unroll
        for (int i = 0; i < THREADS / 32; i++) tot += warp_sum[i];
        // Sum_j relu(c+d_j) = 0.5*(C*c + D) + 0.5*Sum_j|c+d_j|; minus 1 per valid k
        float scalar = 0.5f * ((float)NC * sumc_sh + (float)V * D_sh) - (float)V;
        float result = 0.5f * tot + scalar;
        atomicAdd(out, result * (1.0f / (float)NC));
    }
}

extern "C" void kernel_launch(void* const* d_in, const int* in_sizes, int n_in,
                              void* d_out, int out_size) {
    const float* x   = (const float*)d_in[0];
    const float* m   = (const float*)d_in[1];
    const int*   tgt = (const int*)d_in[2];
    float*       out = (float*)d_out;

    init_out_kernel<<<1, 1>>>(out);
    mlaml_kernel<<<NB, THREADS>>>(x, m, tgt, out);
}

// round 6
// speedup vs baseline: 1.2610x; 1.2610x over previous
#include <cuda_runtime.h>
#include <float.h>

#define NB 256
#define NC 4096
#define NK 32
#define THREADS 256
#define EPT 8           // 256 threads * 8 = 2048 = NC/2 columns per CTA
#define HALves 2

__global__ void init_out_kernel(float* out) { out[0] = 0.0f; }

__global__ __launch_bounds__(THREADS)
void mlaml_kernel(const float* __restrict__ x, const float* __restrict__ m,
                  const int* __restrict__ tgt, float* __restrict__ out) {
    __shared__ float  c_srt[NK];            // sorted descending thresholds
    __shared__ float  pre_plain[NK + 1];    // exclusive prefix sums of c_srt
    __shared__ float  c_tab[NK][32];        // lane-replicated thresholds (bank L = lane L)
    __shared__ float2 pre_tab[NK + 1][32];  // lane-replicated (Cpre[q], (float)q)
    __shared__ float  wsum[THREADS / 32];
    __shared__ int    V_sh;

    const int b    = blockIdx.x;   // row
    const int h    = blockIdx.y;   // column half
    const int tid  = threadIdx.x;
    const int lane = tid & 31;
    const int wid  = tid >> 5;

    const float* xr = x + (size_t)b * NC;
    const float* mr = m + (size_t)b * NC;

    // ---- Load this thread's 8 contiguous d_j = x_j - m_j (start loads early) ----
    const int j0 = h * (NC / 2) + tid * EPT;
    float4 xa = *reinterpret_cast<const float4*>(xr + j0);
    float4 xb = *reinterpret_cast<const float4*>(xr + j0 + 4);
    float4 ma = *reinterpret_cast<const float4*>(mr + j0);
    float4 mb = *reinterpret_cast<const float4*>(mr + j0 + 4);

    float ds[EPT];
    ds[0] = xa.x - ma.x; ds[1] = xa.y - ma.y;
    ds[2] = xa.z - ma.z; ds[3] = xa.w - ma.w;
    ds[4] = xb.x - mb.x; ds[5] = xb.y - mb.y;
    ds[6] = xb.z - mb.z; ds[7] = xb.w - mb.w;

    // ---- Warp 0: gather c_k, sort descending, prefix-sum ----
    if (wid == 0) {
        int   t     = tgt[b * NK + lane];           // int32 targets
        bool  valid = (t > -1);
        float c     = -FLT_MAX;                     // invalid -> never active
        if (valid) c = 1.0f - (__ldg(xr + t) - __ldg(mr + t));
        unsigned vm = __ballot_sync(0xffffffffu, valid);
        if (lane == 0) V_sh = __popc(vm);

        // Bitonic sort ascending across the warp
        float v = c;
        #pragma unroll
        for (int k = 2; k <= 32; k <<= 1) {
            #pragma unroll
            for (int j = k >> 1; j > 0; j >>= 1) {
                float other = __shfl_xor_sync(0xffffffffu, v, j);
                bool  up       = ((lane & k) == 0);
                bool  iAmLower = ((lane & j) == 0);
                float mn = fminf(v, other), mx = fmaxf(v, other);
                v = (iAmLower == up) ? mn : mx;
            }
        }
        // Reverse to descending
        float dv = __shfl_sync(0xffffffffu, v, 31 - lane);
        c_srt[lane] = dv;
        // Inclusive scan of descending values
        float s = dv;
        #pragma unroll
        for (int off = 1; off < 32; off <<= 1) {
            float n = __shfl_up_sync(0xffffffffu, s, off);
            if (lane >= off) s += n;
        }
        pre_plain[lane + 1] = s;
        if (lane == 0) pre_plain[0] = 0.0f;
    }
    __syncthreads();

    // ---- Replicate tables per lane (conflict-free random access later) ----
    #pragma unroll
    for (int e = tid; e < NK * 32; e += THREADS)
        c_tab[e >> 5][e & 31] = c_srt[e >> 5];      // broadcast LDS per warp
    #pragma unroll
    for (int e = tid; e < (NK + 1) * 32; e += THREADS) {
        int idx = e >> 5;
        pre_tab[idx][e & 31] = make_float2(pre_plain[idx], (float)idx);
    }
    __syncthreads();

    // ---- Main loop: per element, branchless binary search over 32 thresholds ----
    float accA = 0.0f;   // sum of Cpre[q]
    float accB = 0.0f;   // sum of q * d
    #pragma unroll
    for (int e = 0; e < EPT; e++) {
        float t = -ds[e];
        int q = 0;
        if (c_tab[q + 15][lane] > t) q += 16;
        if (c_tab[q + 7][lane]  > t) q += 8;
        if (c_tab[q + 3][lane]  > t) q += 4;
        if (c_tab[q + 1][lane]  > t) q += 2;
        if (c_tab[q][lane]      > t) q += 1;
        if (c_tab[q][lane]      > t) q += 1;   // resolves final [q, q+1] interval
        float2 p = pre_tab[q][lane];
        accA += p.x;
        accB  = fmaf(p.y, ds[e], accB);
    }
    float local = accA + accB;

    // ---- Block reduce + atomic ----
    #pragma unroll
    for (int off = 16; off; off >>= 1)
        local += __shfl_xor_sync(0xffffffffu, local, off);
    if (lane == 0) wsum[wid] = local;
    __syncthreads();
    if (tid == 0) {
        float tot = 0.0f;
        #pragma unroll
        for (int i = 0; i < THREADS / 32; i++) tot += wsum[i];
        if (h == 0) tot -= (float)V_sh;   // exclude self terms (exactly 1 each)
        atomicAdd(out, tot * (1.0f / (float)NC));
    }
}

extern "C" void kernel_launch(void* const* d_in, const int* in_sizes, int n_in,
                              void* d_out, int out_size) {
    const float* x   = (const float*)d_in[0];
    const float* m   = (const float*)d_in[1];
    const int*   tgt = (const int*)d_in[2];
    float*       out = (float*)d_out;

    init_out_kernel<<<1, 1>>>(out);
    mlaml_kernel<<<dim3(NB, HALves), THREADS>>>(x, m, tgt, out);
}

// round 7
// speedup vs baseline: 1.2657x; 1.0037x over previous
#include <cuda_runtime.h>
#include <float.h>

#define NB 256
#define NC 4096
#define NK 32
#define THREADS 256
#define EPT 8           // 256 threads * 8 = 2048 = NC/2 columns per CTA
#define NPART (NB * 2)  // one partial per CTA

__device__ float g_partials[NPART];

__global__ __launch_bounds__(THREADS)
void mlaml_kernel(const float* __restrict__ x, const float* __restrict__ m,
                  const int* __restrict__ tgt) {
    __shared__ float  c_srt[NK];            // sorted descending thresholds
    __shared__ float  pre_plain[NK + 1];    // exclusive prefix sums of c_srt
    __shared__ float  c_tab[NK][32];        // lane-replicated (bank L = lane L)
    __shared__ float2 pre_tab[NK + 1][32];  // lane-replicated (Cpre[q], (float)q)
    __shared__ float  wsum[THREADS / 32];
    __shared__ int    V_sh;

    const int b    = blockIdx.x;   // row
    const int h    = blockIdx.y;   // column half
    const int tid  = threadIdx.x;
    const int lane = tid & 31;
    const int wid  = tid >> 5;

    const float* xr = x + (size_t)b * NC;
    const float* mr = m + (size_t)b * NC;

    // ---- Issue the target load FIRST so its DRAM latency overlaps row loads ----
    int t_raw = 0;
    if (wid == 0) t_raw = tgt[b * NK + lane];       // int32 targets

    // ---- Load this thread's 8 contiguous d_j = x_j - m_j ----
    const int j0 = h * (NC / 2) + tid * EPT;
    float4 xa = *reinterpret_cast<const float4*>(xr + j0);
    float4 xb = *reinterpret_cast<const float4*>(xr + j0 + 4);
    float4 ma = *reinterpret_cast<const float4*>(mr + j0);
    float4 mb = *reinterpret_cast<const float4*>(mr + j0 + 4);

    float ds[EPT];
    ds[0] = xa.x - ma.x; ds[1] = xa.y - ma.y;
    ds[2] = xa.z - ma.z; ds[3] = xa.w - ma.w;
    ds[4] = xb.x - mb.x; ds[5] = xb.y - mb.y;
    ds[6] = xb.z - mb.z; ds[7] = xb.w - mb.w;

    // ---- Warp 0: gather c_k = 1 - d_t, sort descending, prefix-sum ----
    if (wid == 0) {
        bool  valid = (t_raw > -1);
        float c     = -FLT_MAX;                     // invalid -> never active
        if (valid) c = 1.0f - (__ldg(xr + t_raw) - __ldg(mr + t_raw));
        unsigned vm = __ballot_sync(0xffffffffu, valid);
        if (lane == 0) V_sh = __popc(vm);

        // Bitonic sort ascending across the warp
        float v = c;
        #pragma unroll
        for (int k = 2; k <= 32; k <<= 1) {
            #pragma unroll
            for (int j = k >> 1; j > 0; j >>= 1) {
                float other = __shfl_xor_sync(0xffffffffu, v, j);
                bool  up       = ((lane & k) == 0);
                bool  iAmLower = ((lane & j) == 0);
                float mn = fminf(v, other), mx = fmaxf(v, other);
                v = (iAmLower == up) ? mn : mx;
            }
        }
        // Reverse to descending
        float dv = __shfl_sync(0xffffffffu, v, 31 - lane);
        c_srt[lane] = dv;
        // Inclusive scan of descending values
        float s = dv;
        #pragma unroll
        for (int off = 1; off < 32; off <<= 1) {
            float n = __shfl_up_sync(0xffffffffu, s, off);
            if (lane >= off) s += n;
        }
        pre_plain[lane + 1] = s;
        if (lane == 0) pre_plain[0] = 0.0f;
    }
    __syncthreads();

    // ---- Replicate tables per lane (conflict-free random access later) ----
    #pragma unroll
    for (int e = tid; e < NK * 32; e += THREADS)
        c_tab[e >> 5][e & 31] = c_srt[e >> 5];
    #pragma unroll
    for (int e = tid; e < (NK + 1) * 32; e += THREADS) {
        int idx = e >> 5;
        pre_tab[idx][e & 31] = make_float2(pre_plain[idx], (float)idx);
    }
    __syncthreads();

    // ---- Main loop: per element, branchless binary search over 32 thresholds ----
    float accA = 0.0f;   // sum of Cpre[q]
    float accB = 0.0f;   // sum of q * d
    #pragma unroll
    for (int e = 0; e < EPT; e++) {
        float t = -ds[e];
        int q = 0;
        if (c_tab[q + 15][lane] > t) q += 16;
        if (c_tab[q + 7][lane]  > t) q += 8;
        if (c_tab[q + 3][lane]  > t) q += 4;
        if (c_tab[q + 1][lane]  > t) q += 2;
        if (c_tab[q][lane]      > t) q += 1;
        if (c_tab[q][lane]      > t) q += 1;   // resolves final [q, q+1] interval
        float2 p = pre_tab[q][lane];
        accA += p.x;
        accB  = fmaf(p.y, ds[e], accB);
    }
    float local = accA + accB;

    // ---- Block reduce; STG partial (no atomics -> no LTS serialization) ----
    #pragma unroll
    for (int off = 16; off; off >>= 1)
        local += __shfl_xor_sync(0xffffffffu, local, off);
    if (lane == 0) wsum[wid] = local;
    __syncthreads();
    if (tid == 0) {
        float tot = 0.0f;
        #pragma unroll
        for (int i = 0; i < THREADS / 32; i++) tot += wsum[i];
        if (h == 0) tot -= (float)V_sh;   // exclude self terms (exactly 1 each)
        g_partials[h * NB + b] = tot;
    }
}

__global__ void finish_kernel(float* __restrict__ out) {
    // One block of 128 threads reduces 512 partials and writes the result.
    const int tid = threadIdx.x;
    float s = 0.0f;
    #pragma unroll
    for (int i = 0; i < NPART / 128; i++)
        s += g_partials[tid + i * 128];
    #pragma unroll
    for (int off = 16; off; off >>= 1)
        s += __shfl_xor_sync(0xffffffffu, s, off);
    __shared__ float ws[4];
    if ((tid & 31) == 0) ws[tid >> 5] = s;
    __syncthreads();
    if (tid == 0) {
        float tot = (ws[0] + ws[1]) + (ws[2] + ws[3]);
        out[0] = tot * (1.0f / (float)NC);
    }
}

extern "C" void kernel_launch(void* const* d_in, const int* in_sizes, int n_in,
                              void* d_out, int out_size) {
    const float* x   = (const float*)d_in[0];
    const float* m   = (const float*)d_in[1];
    const int*   tgt = (const int*)d_in[2];
    float*       out = (float*)d_out;

    mlaml_kernel<<<dim3(NB, 2), THREADS>>>(x, m, tgt);
    finish_kernel<<<1, 128>>>(out);
}